// round 4
// baseline (speedup 1.0000x reference)
#include <cuda_runtime.h>

#define NN 131072          // N_NODES
#define NG 512             // NUM_GRAPHS
#define FIN 54
#define HG 16
#define TLEN 1024
#define NCLS 192

typedef unsigned long long ull;

// ------------------------- scratch (no cudaMalloc allowed) -------------------
__device__ __align__(16) int   g_degi[NN];
__device__ __align__(16) float g_dinv[NN];
__device__ __align__(16) float g_xw[NN * HG];
__device__ __align__(16) float g_agg[NN * HG];
__device__ __align__(16) int   g_starts[NG];
__device__ __align__(16) float g_seq0[(size_t)NG * TLEN * HG];    // 33.5 MB
__device__ __align__(16) float g_seq1[(size_t)NG * TLEN * 64];    // 134 MB
__device__ __align__(16) float g_pooled[NG * 64];

// ------------------------- helpers ------------------------------------------
__device__ __forceinline__ ull pk2(float lo, float hi) {
    ull v; asm("mov.b64 %0, {%1, %2};" : "=l"(v) : "f"(lo), "f"(hi)); return v;
}
__device__ __forceinline__ void upk2(ull v, float& lo, float& hi) {
    asm("mov.b64 {%0, %1}, %2;" : "=f"(lo), "=f"(hi) : "l"(v));
}
// packed dual fp32 FMA (Blackwell f32x2 — 2x FP32 pipe throughput)
#define FMA2(d, a, b) asm("fma.rn.f32x2 %0, %1, %2, %0;" : "+l"(d) : "l"(a), "l"(b))

__device__ __forceinline__ float fsig(float x) {
    x = fminf(fmaxf(x, -30.f), 30.f);
    return __fdividef(1.f, 1.f + __expf(-x));
}
__device__ __forceinline__ float ftanh(float x) {
    x = fminf(fmaxf(x, -15.f), 15.f);
    float e = __expf(2.f * x);
    return __fdividef(e - 1.f, e + 1.f);
}

// ------------------------- GCN ----------------------------------------------
__global__ void zero_kernel() {
    int idx = blockIdx.x * 256 + threadIdx.x;
    if (idx < (int)(NG * TLEN * HG / 4))
        ((float4*)g_seq0)[idx] = make_float4(0.f, 0.f, 0.f, 0.f);
    if (idx < NN) g_degi[idx] = 0;
}

__global__ void deg_kernel(const int* __restrict__ dst, int E) {
    int e = blockIdx.x * 256 + threadIdx.x;
    if (e < E) atomicAdd(&g_degi[dst[e]], 1);
}

__global__ void dinv_kernel() {
    int n = blockIdx.x * 256 + threadIdx.x;
    if (n < NN) g_dinv[n] = rsqrtf((float)(g_degi[n] + 1));  // +1 self-loop
}

// g_xw[n][j] = sum_d f(in[n][d]) * W[d][j]   (f = relu when FROM_AGG)
template<int DIN, bool FROM_AGG>
__global__ void xw_kernel(const float* __restrict__ in, const float* __restrict__ W) {
    __shared__ float Ws[DIN * HG];
    int tid = threadIdx.x;
    for (int i = tid; i < DIN * HG; i += 256) Ws[i] = W[i];
    __syncthreads();
    int idx = blockIdx.x * 256 + tid;
    if (idx >= NN * HG) return;
    int n = idx >> 4, j = idx & 15;
    const float* xr = (FROM_AGG ? (const float*)g_agg : in) + (size_t)n * DIN;
    float acc = 0.f;
#pragma unroll
    for (int d = 0; d < DIN; d++) {
        float v = xr[d];
        if (FROM_AGG) v = fmaxf(v, 0.f);
        acc += v * Ws[d * HG + j];
    }
    g_xw[idx] = acc;
}

// out init = bias + self-loop term (xw[n] * dinv[n]^2)
__global__ void agginit_kernel(const float* __restrict__ bias) {
    int idx = blockIdx.x * 256 + threadIdx.x;
    if (idx >= NN * HG) return;
    int n = idx >> 4, j = idx & 15;
    float di = g_dinv[n];
    g_agg[idx] = bias[j] + g_xw[idx] * di * di;
}

__global__ void scatter_kernel(const int* __restrict__ src, const int* __restrict__ dst, int E) {
    int e = blockIdx.x * 256 + threadIdx.x;
    if (e >= E) return;
    int s = src[e], d = dst[e];
    float nrm = g_dinv[s] * g_dinv[d];
    const float4* xs = (const float4*)(g_xw + (size_t)s * HG);
    float* ad = g_agg + (size_t)d * HG;
#pragma unroll
    for (int q = 0; q < 4; q++) {
        float4 v = xs[q];
        asm volatile("red.global.add.v4.f32 [%0], {%1, %2, %3, %4};" ::
                     "l"(ad + 4 * q),
                     "f"(v.x * nrm), "f"(v.y * nrm), "f"(v.z * nrm), "f"(v.w * nrm)
                     : "memory");
    }
}

// ------------------------- ragged -> padded ---------------------------------
__global__ void starts_kernel(const int* __restrict__ batch) {
    int i = blockIdx.x * 256 + threadIdx.x;
    if (i >= NN) return;
    int b = batch[i];
    int bp = (i == 0) ? -1 : batch[i - 1];
    for (int g = bp + 1; g <= b; ++g) g_starts[g] = i;   // batch is sorted
}

__global__ void pack_kernel(const int* __restrict__ batch) {
    int idx = blockIdx.x * 256 + threadIdx.x;
    if (idx >= NN * 4) return;
    int n = idx >> 2, q = idx & 3;
    int g = batch[n];
    int pos = n - g_starts[g];
    if (pos >= TLEN) return;  // mode="drop"
    float4 v = ((const float4*)(g_agg + (size_t)n * HG))[q];
    v.x = fmaxf(v.x, 0.f); v.y = fmaxf(v.y, 0.f);
    v.z = fmaxf(v.z, 0.f); v.w = fmaxf(v.w, 0.f);
    ((float4*)(g_seq0 + ((size_t)g * TLEN + pos) * HG))[q] = v;
}

// ------------------------- BiLSTM -------------------------------------------
// One block per (row, dir). 128 threads = 128 gates (PyTorch order i,f,g,o).
// Weights in registers (as f32x2 pairs), h/x broadcast from smem, fused input
// projection, double-buffered x with 1-step register prefetch.
template<int DIN, bool IS_L0>
__global__ __launch_bounds__(128) void lstm_kernel(
    const float* __restrict__ wih, const float* __restrict__ whh,
    const float* __restrict__ bih, const float* __restrict__ bhh)
{
    constexpr int NV = DIN / 4;      // float4s per timestep input
    int row = blockIdx.x, dir = blockIdx.y;
    int tid = threadIdx.x;
    const float* X = (IS_L0 ? (const float*)g_seq0 : (const float*)g_seq1)
                     + (size_t)row * TLEN * DIN;
    float* O = g_seq1 + (size_t)row * TLEN * 64 + dir * 32;

    ull wi2[DIN / 2];
    {
        const ull* wp = (const ull*)(wih + ((size_t)dir * 128 + tid) * DIN);
#pragma unroll
        for (int k = 0; k < DIN / 2; k++) wi2[k] = wp[k];
    }
    ull wr2[16];
    {
        const ull* wp = (const ull*)(whh + ((size_t)dir * 128 + tid) * 32);
#pragma unroll
        for (int k = 0; k < 16; k++) wr2[k] = wp[k];
    }
    float bias = bih[dir * 128 + tid] + bhh[dir * 128 + tid];

    __shared__ __align__(16) float h_s[32];
    __shared__ float gact[128];
    __shared__ float4 xbuf[2][NV];

    int t0 = dir ? (TLEN - 1) : 0;
    int dt = dir ? -1 : 1;
    int li = tid - (128 - NV);
    if (tid >= 128 - NV) xbuf[0][li] = ((const float4*)(X + (size_t)t0 * DIN))[li];
    if (tid < 32) h_s[tid] = 0.f;
    __syncthreads();
    float4 pref;
    if (tid >= 128 - NV) pref = ((const float4*)(X + (size_t)(t0 + dt) * DIN))[li];

    float c = 0.f;
    float pool = 0.f;
    bool isg = (tid >= 64 && tid < 96);   // "g" gates use tanh

    for (int s = 0; s < TLEN; s++) {
        int t = t0 + s * dt;
        const ulonglong2* xv = (const ulonglong2*)xbuf[s & 1];
        ull P0 = pk2(bias, 0.f), P1 = pk2(0.f, 0.f), P2 = P1, P3 = P1;
#pragma unroll
        for (int q = 0; q < NV; q++) {
            ulonglong2 xx = xv[q];
            if (q & 1) { FMA2(P2, xx.x, wi2[2 * q]); FMA2(P3, xx.y, wi2[2 * q + 1]); }
            else       { FMA2(P0, xx.x, wi2[2 * q]); FMA2(P1, xx.y, wi2[2 * q + 1]); }
        }
        const ulonglong2* hv = (const ulonglong2*)h_s;
#pragma unroll
        for (int q = 0; q < 8; q++) {
            ulonglong2 hh = hv[q];
            if (q & 1) { FMA2(P2, hh.x, wr2[2 * q]); FMA2(P3, hh.y, wr2[2 * q + 1]); }
            else       { FMA2(P0, hh.x, wr2[2 * q]); FMA2(P1, hh.y, wr2[2 * q + 1]); }
        }
        float f0, f1, f2, f3, f4, f5, f6, f7;
        upk2(P0, f0, f1); upk2(P1, f2, f3); upk2(P2, f4, f5); upk2(P3, f6, f7);
        float acc = ((f0 + f1) + (f2 + f3)) + ((f4 + f5) + (f6 + f7));
        float a = isg ? ftanh(acc) : fsig(acc);
        gact[tid] = a;
        __syncthreads();
        if (tid < 32) {
            float gi = gact[tid], gf = gact[32 + tid], gg = gact[64 + tid], go = gact[96 + tid];
            c = gf * c + gi * gg;
            float hh = go * ftanh(c);
            h_s[tid] = hh;
            if (IS_L0) O[(size_t)t * 64 + tid] = hh;
            else       pool += hh;
        } else if (tid >= 128 - NV && s < TLEN - 1) {
            xbuf[(s + 1) & 1][li] = pref;
        }
        __syncthreads();
        if (tid >= 128 - NV && s < TLEN - 2) {
            pref = ((const float4*)(X + (size_t)(t + 2 * dt) * DIN))[li];
        }
    }
    if (!IS_L0 && tid < 32) g_pooled[row * 64 + dir * 32 + tid] = pool;
}

// ------------------------- FC + mean ----------------------------------------
__global__ void fc_kernel(const float* __restrict__ w, const float* __restrict__ b,
                          float* __restrict__ out) {
    int idx = blockIdx.x * 256 + threadIdx.x;
    if (idx >= NG * NCLS) return;
    int r = idx / NCLS, cc = idx - r * NCLS;
    const float* p = g_pooled + r * 64;
    float acc = 0.f;
#pragma unroll
    for (int k = 0; k < 64; k++) acc += p[k] * w[k * NCLS + cc];
    out[idx] = b[cc] + acc * (1.f / (float)TLEN);
}

// ------------------------- launch -------------------------------------------
extern "C" void kernel_launch(void* const* d_in, const int* in_sizes, int n_in,
                              void* d_out, int out_size) {
    const float* x     = (const float*)d_in[0];
    const int*   ei    = (const int*)d_in[1];
    const int*   batch = (const int*)d_in[2];
    const float* w1    = (const float*)d_in[3];
    const float* b1    = (const float*)d_in[4];
    const float* w2    = (const float*)d_in[5];
    const float* b2    = (const float*)d_in[6];
    const float* l0wih = (const float*)d_in[7];
    const float* l0whh = (const float*)d_in[8];
    const float* l0bih = (const float*)d_in[9];
    const float* l0bhh = (const float*)d_in[10];
    const float* l1wih = (const float*)d_in[11];
    const float* l1whh = (const float*)d_in[12];
    const float* l1bih = (const float*)d_in[13];
    const float* l1bhh = (const float*)d_in[14];
    const float* fcw   = (const float*)d_in[15];
    const float* fcb   = (const float*)d_in[16];
    float* out = (float*)d_out;

    int E = in_sizes[1] / 2;
    const int* src = ei;
    const int* dst = ei + E;

    int zn = NG * TLEN * HG / 4;
    zero_kernel<<<(zn + 255) / 256, 256>>>();
    deg_kernel<<<(E + 255) / 256, 256>>>(dst, E);
    dinv_kernel<<<(NN + 255) / 256, 256>>>();

    // conv1
    xw_kernel<FIN, false><<<(NN * HG + 255) / 256, 256>>>(x, w1);
    agginit_kernel<<<(NN * HG + 255) / 256, 256>>>(b1);
    scatter_kernel<<<(E + 255) / 256, 256>>>(src, dst, E);
    // conv2 (relu of conv1 fused into the read)
    xw_kernel<HG, true><<<(NN * HG + 255) / 256, 256>>>(nullptr, w2);
    agginit_kernel<<<(NN * HG + 255) / 256, 256>>>(b2);
    scatter_kernel<<<(E + 255) / 256, 256>>>(src, dst, E);

    // pack (relu of conv2 fused into the write)
    starts_kernel<<<(NN + 255) / 256, 256>>>(batch);
    pack_kernel<<<(NN * 4 + 255) / 256, 256>>>(batch);

    // BiLSTM x2 (layer1 fuses mean pooling)
    lstm_kernel<HG, true ><<<dim3(NG, 2), 128>>>(l0wih, l0whh, l0bih, l0bhh);
    lstm_kernel<64, false><<<dim3(NG, 2), 128>>>(l1wih, l1whh, l1bih, l1bhh);

    fc_kernel<<<(NG * NCLS + 255) / 256, 256>>>(fcw, fcb, out);
}

// round 5
// speedup vs baseline: 1.5772x; 1.5772x over previous
#include <cuda_runtime.h>

#define NN 131072          // N_NODES
#define NG 512             // NUM_GRAPHS
#define FIN 54
#define HG 16
#define TLEN 1024
#define NCLS 192

typedef unsigned long long ull;

// ------------------------- scratch (no cudaMalloc allowed) -------------------
__device__ __align__(16) int   g_degi[NN];
__device__ __align__(16) float g_dinv[NN];
__device__ __align__(16) float g_xw[NN * HG];
__device__ __align__(16) float g_agg[NN * HG];
__device__ __align__(16) int   g_starts[NG];
__device__ __align__(16) float g_seq0[(size_t)NG * TLEN * HG];      // 33.5 MB (GCN out, padded)
__device__ __align__(16) float g_h0[(size_t)NG * TLEN * 64];        // 134 MB (lstm0 output)
__device__ __align__(16) float g_pre[(size_t)2 * NG * TLEN * 128];  // 537 MB (pre-activations, reused)
__device__ __align__(16) float g_pooled[NG * 64];

// ------------------------- helpers ------------------------------------------
__device__ __forceinline__ ull pk2(float lo, float hi) {
    ull v; asm("mov.b64 %0, {%1, %2};" : "=l"(v) : "f"(lo), "f"(hi)); return v;
}
__device__ __forceinline__ void upk2(ull v, float& lo, float& hi) {
    asm("mov.b64 {%0, %1}, %2;" : "=f"(lo), "=f"(hi) : "l"(v));
}
// packed dual fp32 FMA (Blackwell f32x2 — 2x FP32 pipe throughput)
#define FMA2(d, a, b) asm("fma.rn.f32x2 %0, %1, %2, %0;" : "+l"(d) : "l"(a), "l"(b))

__device__ __forceinline__ float tanh_fast(float x) {
    float y; asm("tanh.approx.f32 %0, %1;" : "=f"(y) : "f"(x)); return y;
}
__device__ __forceinline__ float sig_fast(float x) {
    return fmaf(0.5f, tanh_fast(0.5f * x), 0.5f);
}

// ------------------------- GCN ----------------------------------------------
__global__ void zero_kernel() {
    int idx = blockIdx.x * 256 + threadIdx.x;
    if (idx < (int)(NG * TLEN * HG / 4))
        ((float4*)g_seq0)[idx] = make_float4(0.f, 0.f, 0.f, 0.f);
    if (idx < NN) g_degi[idx] = 0;
}

__global__ void deg_kernel(const int* __restrict__ dst, int E) {
    int e = blockIdx.x * 256 + threadIdx.x;
    if (e < E) atomicAdd(&g_degi[dst[e]], 1);
}

__global__ void dinv_kernel() {
    int n = blockIdx.x * 256 + threadIdx.x;
    if (n < NN) g_dinv[n] = rsqrtf((float)(g_degi[n] + 1));  // +1 self-loop
}

// g_xw[n][j] = sum_d f(in[n][d]) * W[d][j]   (f = relu when FROM_AGG)
template<int DIN, bool FROM_AGG>
__global__ void xw_kernel(const float* __restrict__ in, const float* __restrict__ W) {
    __shared__ float Ws[DIN * HG];
    int tid = threadIdx.x;
    for (int i = tid; i < DIN * HG; i += 256) Ws[i] = W[i];
    __syncthreads();
    int idx = blockIdx.x * 256 + tid;
    if (idx >= NN * HG) return;
    int n = idx >> 4, j = idx & 15;
    const float* xr = (FROM_AGG ? (const float*)g_agg : in) + (size_t)n * DIN;
    float acc = 0.f;
#pragma unroll
    for (int d = 0; d < DIN; d++) {
        float v = xr[d];
        if (FROM_AGG) v = fmaxf(v, 0.f);
        acc += v * Ws[d * HG + j];
    }
    g_xw[idx] = acc;
}

// out init = bias + self-loop term (xw[n] * dinv[n]^2)
__global__ void agginit_kernel(const float* __restrict__ bias) {
    int idx = blockIdx.x * 256 + threadIdx.x;
    if (idx >= NN * HG) return;
    int n = idx >> 4, j = idx & 15;
    float di = g_dinv[n];
    g_agg[idx] = bias[j] + g_xw[idx] * di * di;
}

__global__ void scatter_kernel(const int* __restrict__ src, const int* __restrict__ dst, int E) {
    int e = blockIdx.x * 256 + threadIdx.x;
    if (e >= E) return;
    int s = src[e], d = dst[e];
    float nrm = g_dinv[s] * g_dinv[d];
    const float4* xs = (const float4*)(g_xw + (size_t)s * HG);
    float* ad = g_agg + (size_t)d * HG;
#pragma unroll
    for (int q = 0; q < 4; q++) {
        float4 v = xs[q];
        asm volatile("red.global.add.v4.f32 [%0], {%1, %2, %3, %4};" ::
                     "l"(ad + 4 * q),
                     "f"(v.x * nrm), "f"(v.y * nrm), "f"(v.z * nrm), "f"(v.w * nrm)
                     : "memory");
    }
}

// ------------------------- ragged -> padded ---------------------------------
__global__ void starts_kernel(const int* __restrict__ batch) {
    int i = blockIdx.x * 256 + threadIdx.x;
    if (i >= NN) return;
    int b = batch[i];
    int bp = (i == 0) ? -1 : batch[i - 1];
    for (int g = bp + 1; g <= b; ++g) g_starts[g] = i;   // batch is sorted
}

__global__ void pack_kernel(const int* __restrict__ batch) {
    int idx = blockIdx.x * 256 + threadIdx.x;
    if (idx >= NN * 4) return;
    int n = idx >> 2, q = idx & 3;
    int g = batch[n];
    int pos = n - g_starts[g];
    if (pos >= TLEN) return;  // mode="drop"
    float4 v = ((const float4*)(g_agg + (size_t)n * HG))[q];
    v.x = fmaxf(v.x, 0.f); v.y = fmaxf(v.y, 0.f);
    v.z = fmaxf(v.z, 0.f); v.w = fmaxf(v.w, 0.f);
    ((float4*)(g_seq0 + ((size_t)g * TLEN + pos) * HG))[q] = v;
}

// ------------------------- LSTM input projection (batch GEMM) ----------------
// pre[dir][row][t][j*4+g] = bias[g*32+j] + sum_k X[row][t][k] * wih[dir][g*32+j][k]
// Gate-interleaved output so the recurrence thread j loads one float4 per step.
template<int DIN>
__global__ __launch_bounds__(256) void gemm_pre_kernel(
    const float* __restrict__ X,      // [NG][TLEN][DIN]
    const float* __restrict__ wih,    // [2][128][DIN]
    const float* __restrict__ bih, const float* __restrict__ bhh) // [2][128]
{
    constexpr int WPAD = DIN + 4;     // pad for conflict-free LDS.128
    constexpr int TT = 64;            // timesteps per block
    constexpr int TPG = 8;            // timesteps per thread-group iteration
    __shared__ float Ws[128 * WPAD];
    __shared__ float Bs[128];
    __shared__ float Xs[TT * DIN];

    int dir = blockIdx.z, row = blockIdx.y;
    int tb = blockIdx.x * TT;
    int tid = threadIdx.x;

    const float* Wg = wih + (size_t)dir * 128 * DIN;
    for (int i = tid; i < 128 * DIN; i += 256) {
        int r = i / DIN, k = i - r * DIN;
        Ws[r * WPAD + k] = Wg[i];
    }
    if (tid < 128) Bs[tid] = bih[dir * 128 + tid] + bhh[dir * 128 + tid];
    const float4* Xg = (const float4*)(X + ((size_t)row * TLEN + tb) * DIN);
    for (int i = tid; i < TT * DIN / 4; i += 256) ((float4*)Xs)[i] = Xg[i];
    __syncthreads();

    int j = tid & 31, grp = tid >> 5;            // 8 groups x 32 units
    const float* xb = Xs + grp * TPG * DIN;
    const float* w0 = Ws + (0 * 32 + j) * WPAD;
    const float* w1 = Ws + (1 * 32 + j) * WPAD;
    const float* w2 = Ws + (2 * 32 + j) * WPAD;
    const float* w3 = Ws + (3 * 32 + j) * WPAD;

    ull acc[TPG][4];
#pragma unroll
    for (int tt = 0; tt < TPG; tt++)
#pragma unroll
        for (int g = 0; g < 4; g++) acc[tt][g] = 0ull;

#pragma unroll
    for (int k = 0; k < DIN; k += 4) {
        ulonglong2 wv0 = *(const ulonglong2*)(w0 + k);
        ulonglong2 wv1 = *(const ulonglong2*)(w1 + k);
        ulonglong2 wv2 = *(const ulonglong2*)(w2 + k);
        ulonglong2 wv3 = *(const ulonglong2*)(w3 + k);
#pragma unroll
        for (int tt = 0; tt < TPG; tt++) {
            ulonglong2 xv = *(const ulonglong2*)(xb + tt * DIN + k);
            FMA2(acc[tt][0], xv.x, wv0.x); FMA2(acc[tt][0], xv.y, wv0.y);
            FMA2(acc[tt][1], xv.x, wv1.x); FMA2(acc[tt][1], xv.y, wv1.y);
            FMA2(acc[tt][2], xv.x, wv2.x); FMA2(acc[tt][2], xv.y, wv2.y);
            FMA2(acc[tt][3], xv.x, wv3.x); FMA2(acc[tt][3], xv.y, wv3.y);
        }
    }

    float b0 = Bs[j], b1 = Bs[32 + j], b2 = Bs[64 + j], b3 = Bs[96 + j];
    float4* Og = (float4*)(g_pre + (((size_t)dir * NG + row) * TLEN + tb + grp * TPG) * 128) + j;
#pragma unroll
    for (int tt = 0; tt < TPG; tt++) {
        float lo, hi; float4 o;
        upk2(acc[tt][0], lo, hi); o.x = lo + hi + b0;
        upk2(acc[tt][1], lo, hi); o.y = lo + hi + b1;
        upk2(acc[tt][2], lo, hi); o.z = lo + hi + b2;
        upk2(acc[tt][3], lo, hi); o.w = lo + hi + b3;
        Og[(size_t)tt * 32] = o;
    }
}

// ------------------------- LSTM recurrence -----------------------------------
// One warp per (row, dir). Thread j owns hidden unit j: all 4 of its gates and
// the c/h update are thread-local. Only one __syncwarp per step (double-buffered
// h in smem). Recurrent weights in 128 registers. pre prefetched 2 steps ahead.
template<bool IS_L0>
__global__ __launch_bounds__(32) void lstm_rec_kernel(const float* __restrict__ whh)
{
    int row = blockIdx.x, dir = blockIdx.y;
    int j = threadIdx.x;
    const float4* P = (const float4*)(g_pre + ((size_t)dir * NG + row) * TLEN * 128) + j;
    float* O = g_h0 + (size_t)row * TLEN * 64 + dir * 32 + j;

    ulonglong2 w[4][8];
#pragma unroll
    for (int g = 0; g < 4; g++) {
        const ulonglong2* wp = (const ulonglong2*)(whh + ((size_t)dir * 128 + g * 32 + j) * 32);
#pragma unroll
        for (int q = 0; q < 8; q++) w[g][q] = wp[q];
    }

    __shared__ __align__(16) float h_s[2][32];
    h_s[0][j] = 0.f;
    __syncwarp();

    int t0 = dir ? (TLEN - 1) : 0;
    int dt = dir ? -1 : 1;
    float4 p0 = P[(size_t)t0 * 32];
    float4 p1 = P[(size_t)(t0 + dt) * 32];
    float4 p2 = make_float4(0.f, 0.f, 0.f, 0.f);
    float c = 0.f, pool = 0.f;
    int buf = 0;

    for (int s = 0; s < TLEN; s++) {
        int t = t0 + s * dt;
        if (s + 2 < TLEN) p2 = P[(size_t)(t + 2 * dt) * 32];

        ull a0 = pk2(p0.x, 0.f), a1 = pk2(p0.y, 0.f);
        ull a2 = pk2(p0.z, 0.f), a3 = pk2(p0.w, 0.f);
        const ulonglong2* hv = (const ulonglong2*)h_s[buf];
#pragma unroll
        for (int q = 0; q < 8; q++) {
            ulonglong2 hh = hv[q];
            FMA2(a0, hh.x, w[0][q].x); FMA2(a0, hh.y, w[0][q].y);
            FMA2(a1, hh.x, w[1][q].x); FMA2(a1, hh.y, w[1][q].y);
            FMA2(a2, hh.x, w[2][q].x); FMA2(a2, hh.y, w[2][q].y);
            FMA2(a3, hh.x, w[3][q].x); FMA2(a3, hh.y, w[3][q].y);
        }
        float lo, hi;
        upk2(a0, lo, hi); float gi = sig_fast(lo + hi);
        upk2(a1, lo, hi); float gf = sig_fast(lo + hi);
        upk2(a2, lo, hi); float gg = tanh_fast(lo + hi);
        upk2(a3, lo, hi); float go = sig_fast(lo + hi);
        c = gf * c + gi * gg;
        float h = go * tanh_fast(c);
        if (IS_L0) O[(size_t)t * 64] = h;
        else       pool += h;
        h_s[buf ^ 1][j] = h;
        __syncwarp();
        buf ^= 1;
        p0 = p1; p1 = p2;
    }
    if (!IS_L0) g_pooled[row * 64 + dir * 32 + j] = pool;
}

// ------------------------- FC + mean ----------------------------------------
__global__ void fc_kernel(const float* __restrict__ w, const float* __restrict__ b,
                          float* __restrict__ out) {
    int idx = blockIdx.x * 256 + threadIdx.x;
    if (idx >= NG * NCLS) return;
    int r = idx / NCLS, cc = idx - r * NCLS;
    const float* p = g_pooled + r * 64;
    float acc = 0.f;
#pragma unroll
    for (int k = 0; k < 64; k++) acc += p[k] * w[k * NCLS + cc];
    out[idx] = b[cc] + acc * (1.f / (float)TLEN);
}

// ------------------------- launch -------------------------------------------
extern "C" void kernel_launch(void* const* d_in, const int* in_sizes, int n_in,
                              void* d_out, int out_size) {
    const float* x     = (const float*)d_in[0];
    const int*   ei    = (const int*)d_in[1];
    const int*   batch = (const int*)d_in[2];
    const float* w1    = (const float*)d_in[3];
    const float* b1    = (const float*)d_in[4];
    const float* w2    = (const float*)d_in[5];
    const float* b2    = (const float*)d_in[6];
    const float* l0wih = (const float*)d_in[7];
    const float* l0whh = (const float*)d_in[8];
    const float* l0bih = (const float*)d_in[9];
    const float* l0bhh = (const float*)d_in[10];
    const float* l1wih = (const float*)d_in[11];
    const float* l1whh = (const float*)d_in[12];
    const float* l1bih = (const float*)d_in[13];
    const float* l1bhh = (const float*)d_in[14];
    const float* fcw   = (const float*)d_in[15];
    const float* fcb   = (const float*)d_in[16];
    float* out = (float*)d_out;

    int E = in_sizes[1] / 2;
    const int* src = ei;
    const int* dst = ei + E;

    float* seq0_p; cudaGetSymbolAddress((void**)&seq0_p, g_seq0);
    float* h0_p;   cudaGetSymbolAddress((void**)&h0_p, g_h0);

    int zn = NG * TLEN * HG / 4;
    zero_kernel<<<(zn + 255) / 256, 256>>>();
    deg_kernel<<<(E + 255) / 256, 256>>>(dst, E);
    dinv_kernel<<<(NN + 255) / 256, 256>>>();

    // conv1
    xw_kernel<FIN, false><<<(NN * HG + 255) / 256, 256>>>(x, w1);
    agginit_kernel<<<(NN * HG + 255) / 256, 256>>>(b1);
    scatter_kernel<<<(E + 255) / 256, 256>>>(src, dst, E);
    // conv2 (relu of conv1 fused into the read)
    xw_kernel<HG, true><<<(NN * HG + 255) / 256, 256>>>(nullptr, w2);
    agginit_kernel<<<(NN * HG + 255) / 256, 256>>>(b2);
    scatter_kernel<<<(E + 255) / 256, 256>>>(src, dst, E);

    // pack (relu of conv2 fused into the write)
    starts_kernel<<<(NN + 255) / 256, 256>>>(batch);
    pack_kernel<<<(NN * 4 + 255) / 256, 256>>>(batch);

    // BiLSTM layer 0: input projection GEMM, then 1-warp recurrence
    gemm_pre_kernel<HG><<<dim3(TLEN / 64, NG, 2), 256>>>(seq0_p, l0wih, l0bih, l0bhh);
    lstm_rec_kernel<true><<<dim3(NG, 2), 32>>>(l0whh);

    // BiLSTM layer 1 (fuses mean pooling)
    gemm_pre_kernel<64><<<dim3(TLEN / 64, NG, 2), 256>>>(h0_p, l1wih, l1bih, l1bhh);
    lstm_rec_kernel<false><<<dim3(NG, 2), 32>>>(l1whh);

    fc_kernel<<<(NG * NCLS + 255) / 256, 256>>>(fcw, fcb, out);
}

// round 6
// speedup vs baseline: 1.6461x; 1.0437x over previous
#include <cuda_runtime.h>

#define NN 131072          // N_NODES
#define NG 512             // NUM_GRAPHS
#define FIN 54
#define HG 16
#define TLEN 1024
#define NCLS 192
#define EMAX 4194304

typedef unsigned long long ull;

// ------------------------- scratch (no cudaMalloc allowed) -------------------
__device__ __align__(16) int   g_degi[NN];
__device__ __align__(16) float g_dinv[NN];
__device__ __align__(16) int   g_eoff[NN];
__device__ __align__(16) int   g_ecur[NN];
__device__ __align__(16) int   g_part[512];
__device__ __align__(16) int   g_psum[512];
__device__ __align__(16) int2  g_epk[EMAX];                         // {src, dinv[src]}
__device__ __align__(16) float g_xw[NN * HG];
__device__ __align__(16) float g_agg[NN * HG];
__device__ __align__(16) int   g_starts[NG];
__device__ __align__(16) float g_seq0[(size_t)NG * TLEN * HG];      // 33.5 MB
__device__ __align__(16) float g_h0[(size_t)NG * TLEN * 64];        // 134 MB
__device__ __align__(16) float g_pre[(size_t)2 * NG * TLEN * 128];  // 537 MB
__device__ __align__(16) float g_pooled[NG * 64];

// ------------------------- helpers ------------------------------------------
__device__ __forceinline__ ull pk2(float lo, float hi) {
    ull v; asm("mov.b64 %0, {%1, %2};" : "=l"(v) : "f"(lo), "f"(hi)); return v;
}
__device__ __forceinline__ void upk2(ull v, float& lo, float& hi) {
    asm("mov.b64 {%0, %1}, %2;" : "=f"(lo), "=f"(hi) : "l"(v));
}
#define FMA2(d, a, b) asm("fma.rn.f32x2 %0, %1, %2, %0;" : "+l"(d) : "l"(a), "l"(b))

__device__ __forceinline__ float tanh_fast(float x) {
    float y; asm("tanh.approx.f32 %0, %1;" : "=f"(y) : "f"(x)); return y;
}
__device__ __forceinline__ float sig_fast(float x) {
    return fmaf(0.5f, tanh_fast(0.5f * x), 0.5f);
}

// ------------------------- init + degree + scan + fill -----------------------
__global__ void init_kernel() {
    int idx = blockIdx.x * 256 + threadIdx.x;
    if (idx < (int)(NG * TLEN * HG / 4))
        ((float4*)g_seq0)[idx] = make_float4(0.f, 0.f, 0.f, 0.f);
    if (idx < NN) g_degi[idx] = 0;
}

__global__ void deg_kernel(const int* __restrict__ dst, int E) {
    int e = blockIdx.x * 256 + threadIdx.x;
    if (e < E) atomicAdd(&g_degi[dst[e]], 1);
}

// block sums of g_degi (256 per block, 512 blocks)
__global__ void scan1_kernel() {
    __shared__ int sh[256];
    int tid = threadIdx.x;
    sh[tid] = g_degi[blockIdx.x * 256 + tid];
    __syncthreads();
    for (int o = 128; o > 0; o >>= 1) {
        if (tid < o) sh[tid] += sh[tid + o];
        __syncthreads();
    }
    if (tid == 0) g_part[blockIdx.x] = sh[0];
}

// exclusive scan of 512 partials (single block)
__global__ void scan2_kernel() {
    __shared__ int sh[512];
    int tid = threadIdx.x;
    sh[tid] = g_part[tid];
    __syncthreads();
    int v;
    for (int o = 1; o < 512; o <<= 1) {
        v = (tid >= o) ? sh[tid - o] : 0;
        __syncthreads();
        sh[tid] += v;
        __syncthreads();
    }
    g_psum[tid] = (tid == 0) ? 0 : sh[tid - 1];
}

// per-node exclusive offsets + dinv
__global__ void scan3_kernel() {
    __shared__ int sh[256];
    int tid = threadIdx.x;
    int n = blockIdx.x * 256 + tid;
    int d = g_degi[n];
    sh[tid] = d;
    __syncthreads();
    int v;
    for (int o = 1; o < 256; o <<= 1) {
        v = (tid >= o) ? sh[tid - o] : 0;
        __syncthreads();
        sh[tid] += v;
        __syncthreads();
    }
    int off = g_psum[blockIdx.x] + sh[tid] - d;   // exclusive
    g_eoff[n] = off;
    g_ecur[n] = off;
    g_dinv[n] = rsqrtf((float)(d + 1));           // +1 self-loop
}

__global__ void fill_kernel(const int* __restrict__ src, const int* __restrict__ dst, int E) {
    int e = blockIdx.x * 256 + threadIdx.x;
    if (e >= E) return;
    int s = src[e], d = dst[e];
    int pos = atomicAdd(&g_ecur[d], 1);
    g_epk[pos] = make_int2(s, __float_as_int(g_dinv[s]));
}

// ------------------------- GCN feature transform -----------------------------
// g_xw[n][j] = sum_d x[n][d] * W[d][j]   (16 nodes per block, smem-staged)
__global__ __launch_bounds__(256) void xw1_kernel(const float* __restrict__ x,
                                                  const float* __restrict__ W) {
    __shared__ float Ws[FIN * HG];
    __shared__ float Xs[16 * FIN];
    int tid = threadIdx.x;
    for (int i = tid; i < FIN * HG; i += 256) Ws[i] = W[i];
    size_t base = (size_t)blockIdx.x * 16 * FIN;
    for (int i = tid; i < 16 * FIN; i += 256) Xs[i] = x[base + i];
    __syncthreads();
    int nl = tid >> 4, j = tid & 15;
    const float* xr = Xs + nl * FIN;
    float acc = 0.f;
#pragma unroll
    for (int d = 0; d < FIN; d++) acc = fmaf(xr[d], Ws[d * HG + j], acc);
    g_xw[(size_t)blockIdx.x * 256 + tid] = acc;
}

// g_xw[n][j] = sum_d relu(g_agg[n][d]) * W[d][j]
__global__ __launch_bounds__(256) void xw2_kernel(const float* __restrict__ W) {
    __shared__ float Ws[HG * HG];
    __shared__ float Xs[16 * HG];
    int tid = threadIdx.x;
    if (tid < HG * HG) Ws[tid] = W[tid];
    size_t base = (size_t)blockIdx.x * 16 * HG;
    if (tid < 64) ((float4*)Xs)[tid] = ((const float4*)(g_agg + base))[tid];
    __syncthreads();
    int nl = tid >> 4, j = tid & 15;
    const float* xr = Xs + nl * HG;
    float acc = 0.f;
#pragma unroll
    for (int d = 0; d < HG; d++) acc = fmaf(fmaxf(xr[d], 0.f), Ws[d * HG + j], acc);
    g_xw[(size_t)blockIdx.x * 256 + tid] = acc;
}

// ------------------------- gather-based conv ---------------------------------
// out[n] = bias + dinv[n] * sum_{e->n} dinv[s]*xw[s] + dinv[n]^2 * xw[n]
__global__ __launch_bounds__(256) void conv_kernel(const float* __restrict__ bias) {
    int n = blockIdx.x * 256 + threadIdx.x;
    if (n >= NN) return;
    int e0 = g_eoff[n];
    int e1 = e0 + g_degi[n];
    float4 a0 = make_float4(0.f, 0.f, 0.f, 0.f), a1 = a0, a2 = a0, a3 = a0;
#pragma unroll 4
    for (int e = e0; e < e1; e++) {
        int2 pk = g_epk[e];
        int s = pk.x;
        float nr = __int_as_float(pk.y);
        const float4* xs = (const float4*)(g_xw + (size_t)s * HG);
        float4 v0 = xs[0], v1 = xs[1], v2 = xs[2], v3 = xs[3];
        a0.x = fmaf(nr, v0.x, a0.x); a0.y = fmaf(nr, v0.y, a0.y);
        a0.z = fmaf(nr, v0.z, a0.z); a0.w = fmaf(nr, v0.w, a0.w);
        a1.x = fmaf(nr, v1.x, a1.x); a1.y = fmaf(nr, v1.y, a1.y);
        a1.z = fmaf(nr, v1.z, a1.z); a1.w = fmaf(nr, v1.w, a1.w);
        a2.x = fmaf(nr, v2.x, a2.x); a2.y = fmaf(nr, v2.y, a2.y);
        a2.z = fmaf(nr, v2.z, a2.z); a2.w = fmaf(nr, v2.w, a2.w);
        a3.x = fmaf(nr, v3.x, a3.x); a3.y = fmaf(nr, v3.y, a3.y);
        a3.z = fmaf(nr, v3.z, a3.z); a3.w = fmaf(nr, v3.w, a3.w);
    }
    float di = g_dinv[n];
    float d2 = di * di;
    const float4* xn = (const float4*)(g_xw + (size_t)n * HG);
    const float4* bb = (const float4*)bias;
    float4* out = (float4*)(g_agg + (size_t)n * HG);
    float4 q, b, w;
#define EMIT(acc, k) \
    w = xn[k]; b = bb[k]; \
    q.x = b.x + di * acc.x + d2 * w.x; q.y = b.y + di * acc.y + d2 * w.y; \
    q.z = b.z + di * acc.z + d2 * w.z; q.w = b.w + di * acc.w + d2 * w.w; \
    out[k] = q;
    EMIT(a0, 0) EMIT(a1, 1) EMIT(a2, 2) EMIT(a3, 3)
#undef EMIT
}

// ------------------------- ragged -> padded ---------------------------------
__global__ void starts_kernel(const int* __restrict__ batch) {
    int i = blockIdx.x * 256 + threadIdx.x;
    if (i >= NN) return;
    int b = batch[i];
    int bp = (i == 0) ? -1 : batch[i - 1];
    for (int g = bp + 1; g <= b; ++g) g_starts[g] = i;   // batch is sorted
}

__global__ void pack_kernel(const int* __restrict__ batch) {
    int idx = blockIdx.x * 256 + threadIdx.x;
    if (idx >= NN * 4) return;
    int n = idx >> 2, q = idx & 3;
    int g = batch[n];
    int pos = n - g_starts[g];
    if (pos >= TLEN) return;  // mode="drop"
    float4 v = ((const float4*)(g_agg + (size_t)n * HG))[q];
    v.x = fmaxf(v.x, 0.f); v.y = fmaxf(v.y, 0.f);
    v.z = fmaxf(v.z, 0.f); v.w = fmaxf(v.w, 0.f);
    ((float4*)(g_seq0 + ((size_t)g * TLEN + pos) * HG))[q] = v;
}

// ------------------------- LSTM input projection (batch GEMM) ----------------
template<int DIN>
__global__ __launch_bounds__(256) void gemm_pre_kernel(
    const float* __restrict__ X,      // [NG][TLEN][DIN]
    const float* __restrict__ wih,    // [2][128][DIN]
    const float* __restrict__ bih, const float* __restrict__ bhh) // [2][128]
{
    constexpr int WPAD = DIN + 4;
    constexpr int TT = 64;
    constexpr int TPG = 8;
    __shared__ float Ws[128 * WPAD];
    __shared__ float Bs[128];
    __shared__ float Xs[TT * DIN];

    int dir = blockIdx.z, row = blockIdx.y;
    int tb = blockIdx.x * TT;
    int tid = threadIdx.x;

    const float* Wg = wih + (size_t)dir * 128 * DIN;
    for (int i = tid; i < 128 * DIN; i += 256) {
        int r = i / DIN, k = i - r * DIN;
        Ws[r * WPAD + k] = Wg[i];
    }
    if (tid < 128) Bs[tid] = bih[dir * 128 + tid] + bhh[dir * 128 + tid];
    const float4* Xg = (const float4*)(X + ((size_t)row * TLEN + tb) * DIN);
    for (int i = tid; i < TT * DIN / 4; i += 256) ((float4*)Xs)[i] = Xg[i];
    __syncthreads();

    int j = tid & 31, grp = tid >> 5;
    const float* xb = Xs + grp * TPG * DIN;
    const float* w0 = Ws + (0 * 32 + j) * WPAD;
    const float* w1 = Ws + (1 * 32 + j) * WPAD;
    const float* w2 = Ws + (2 * 32 + j) * WPAD;
    const float* w3 = Ws + (3 * 32 + j) * WPAD;

    ull acc[TPG][4];
#pragma unroll
    for (int tt = 0; tt < TPG; tt++)
#pragma unroll
        for (int g = 0; g < 4; g++) acc[tt][g] = 0ull;

#pragma unroll
    for (int k = 0; k < DIN; k += 4) {
        ulonglong2 wv0 = *(const ulonglong2*)(w0 + k);
        ulonglong2 wv1 = *(const ulonglong2*)(w1 + k);
        ulonglong2 wv2 = *(const ulonglong2*)(w2 + k);
        ulonglong2 wv3 = *(const ulonglong2*)(w3 + k);
#pragma unroll
        for (int tt = 0; tt < TPG; tt++) {
            ulonglong2 xv = *(const ulonglong2*)(xb + tt * DIN + k);
            FMA2(acc[tt][0], xv.x, wv0.x); FMA2(acc[tt][0], xv.y, wv0.y);
            FMA2(acc[tt][1], xv.x, wv1.x); FMA2(acc[tt][1], xv.y, wv1.y);
            FMA2(acc[tt][2], xv.x, wv2.x); FMA2(acc[tt][2], xv.y, wv2.y);
            FMA2(acc[tt][3], xv.x, wv3.x); FMA2(acc[tt][3], xv.y, wv3.y);
        }
    }

    float b0 = Bs[j], b1 = Bs[32 + j], b2 = Bs[64 + j], b3 = Bs[96 + j];
    float4* Og = (float4*)(g_pre + (((size_t)dir * NG + row) * TLEN + tb + grp * TPG) * 128) + j;
#pragma unroll
    for (int tt = 0; tt < TPG; tt++) {
        float lo, hi; float4 o;
        upk2(acc[tt][0], lo, hi); o.x = lo + hi + b0;
        upk2(acc[tt][1], lo, hi); o.y = lo + hi + b1;
        upk2(acc[tt][2], lo, hi); o.z = lo + hi + b2;
        upk2(acc[tt][3], lo, hi); o.w = lo + hi + b3;
        Og[(size_t)tt * 32] = o;
    }
}

// ------------------------- LSTM recurrence -----------------------------------
template<bool IS_L0>
__global__ __launch_bounds__(32) void lstm_rec_kernel(const float* __restrict__ whh)
{
    int row = blockIdx.x, dir = blockIdx.y;
    int j = threadIdx.x;
    const float4* P = (const float4*)(g_pre + ((size_t)dir * NG + row) * TLEN * 128) + j;
    float* O = g_h0 + (size_t)row * TLEN * 64 + dir * 32 + j;

    ulonglong2 w[4][8];
#pragma unroll
    for (int g = 0; g < 4; g++) {
        const ulonglong2* wp = (const ulonglong2*)(whh + ((size_t)dir * 128 + g * 32 + j) * 32);
#pragma unroll
        for (int q = 0; q < 8; q++) w[g][q] = wp[q];
    }

    __shared__ __align__(16) float h_s[2][32];
    h_s[0][j] = 0.f;
    __syncwarp();

    int t0 = dir ? (TLEN - 1) : 0;
    int dt = dir ? -1 : 1;
    float4 p0 = P[(size_t)t0 * 32];
    float4 p1 = P[(size_t)(t0 + dt) * 32];
    float4 p2 = make_float4(0.f, 0.f, 0.f, 0.f);
    float c = 0.f, pool = 0.f;
    int buf = 0;

    for (int s = 0; s < TLEN; s++) {
        int t = t0 + s * dt;
        if (s + 2 < TLEN) p2 = P[(size_t)(t + 2 * dt) * 32];

        ull a0 = pk2(p0.x, 0.f), a1 = pk2(p0.y, 0.f);
        ull a2 = pk2(p0.z, 0.f), a3 = pk2(p0.w, 0.f);
        const ulonglong2* hv = (const ulonglong2*)h_s[buf];
#pragma unroll
        for (int q = 0; q < 8; q++) {
            ulonglong2 hh = hv[q];
            FMA2(a0, hh.x, w[0][q].x); FMA2(a0, hh.y, w[0][q].y);
            FMA2(a1, hh.x, w[1][q].x); FMA2(a1, hh.y, w[1][q].y);
            FMA2(a2, hh.x, w[2][q].x); FMA2(a2, hh.y, w[2][q].y);
            FMA2(a3, hh.x, w[3][q].x); FMA2(a3, hh.y, w[3][q].y);
        }
        float lo, hi;
        upk2(a0, lo, hi); float gi = sig_fast(lo + hi);
        upk2(a1, lo, hi); float gf = sig_fast(lo + hi);
        upk2(a2, lo, hi); float gg = tanh_fast(lo + hi);
        upk2(a3, lo, hi); float go = sig_fast(lo + hi);
        c = gf * c + gi * gg;
        float h = go * tanh_fast(c);
        if (IS_L0) O[(size_t)t * 64] = h;
        else       pool += h;
        h_s[buf ^ 1][j] = h;
        __syncwarp();
        buf ^= 1;
        p0 = p1; p1 = p2;
    }
    if (!IS_L0) g_pooled[row * 64 + dir * 32 + j] = pool;
}

// ------------------------- FC + mean ----------------------------------------
__global__ void fc_kernel(const float* __restrict__ w, const float* __restrict__ b,
                          float* __restrict__ out) {
    int idx = blockIdx.x * 256 + threadIdx.x;
    if (idx >= NG * NCLS) return;
    int r = idx / NCLS, cc = idx - r * NCLS;
    const float* p = g_pooled + r * 64;
    float acc = 0.f;
#pragma unroll
    for (int k = 0; k < 64; k++) acc += p[k] * w[k * NCLS + cc];
    out[idx] = b[cc] + acc * (1.f / (float)TLEN);
}

// ------------------------- launch -------------------------------------------
extern "C" void kernel_launch(void* const* d_in, const int* in_sizes, int n_in,
                              void* d_out, int out_size) {
    const float* x     = (const float*)d_in[0];
    const int*   ei    = (const int*)d_in[1];
    const int*   batch = (const int*)d_in[2];
    const float* w1    = (const float*)d_in[3];
    const float* b1    = (const float*)d_in[4];
    const float* w2    = (const float*)d_in[5];
    const float* b2    = (const float*)d_in[6];
    const float* l0wih = (const float*)d_in[7];
    const float* l0whh = (const float*)d_in[8];
    const float* l0bih = (const float*)d_in[9];
    const float* l0bhh = (const float*)d_in[10];
    const float* l1wih = (const float*)d_in[11];
    const float* l1whh = (const float*)d_in[12];
    const float* l1bih = (const float*)d_in[13];
    const float* l1bhh = (const float*)d_in[14];
    const float* fcw   = (const float*)d_in[15];
    const float* fcb   = (const float*)d_in[16];
    float* out = (float*)d_out;

    int E = in_sizes[1] / 2;
    const int* src = ei;
    const int* dst = ei + E;

    float* seq0_p; cudaGetSymbolAddress((void**)&seq0_p, g_seq0);
    float* h0_p;   cudaGetSymbolAddress((void**)&h0_p, g_h0);

    // CSR build (sort edges by dst, once; reused by both convs)
    init_kernel<<<8192, 256>>>();
    deg_kernel<<<(E + 255) / 256, 256>>>(dst, E);
    scan1_kernel<<<512, 256>>>();
    scan2_kernel<<<1, 512>>>();
    scan3_kernel<<<512, 256>>>();
    fill_kernel<<<(E + 255) / 256, 256>>>(src, dst, E);

    // conv1 + conv2 (gather-based, bias+self fused; relu fused into readers)
    xw1_kernel<<<NN / 16, 256>>>(x, w1);
    conv_kernel<<<NN / 256, 256>>>(b1);
    xw2_kernel<<<NN / 16, 256>>>(w2);
    conv_kernel<<<NN / 256, 256>>>(b2);

    // pack (relu of conv2 fused into the write)
    starts_kernel<<<(NN + 255) / 256, 256>>>(batch);
    pack_kernel<<<(NN * 4 + 255) / 256, 256>>>(batch);

    // BiLSTM layer 0
    gemm_pre_kernel<HG><<<dim3(TLEN / 64, NG, 2), 256>>>(seq0_p, l0wih, l0bih, l0bhh);
    lstm_rec_kernel<true><<<dim3(NG, 2), 32>>>(l0whh);

    // BiLSTM layer 1 (fuses mean pooling)
    gemm_pre_kernel<64><<<dim3(TLEN / 64, NG, 2), 256>>>(h0_p, l1wih, l1bih, l1bhh);
    lstm_rec_kernel<false><<<dim3(NG, 2), 32>>>(l1whh);

    fc_kernel<<<(NG * NCLS + 255) / 256, 256>>>(fcw, fcb, out);
}

// round 7
// speedup vs baseline: 1.9022x; 1.1556x over previous
#include <cuda_runtime.h>

#define NN 131072          // N_NODES
#define NG 512             // NUM_GRAPHS
#define FIN 54
#define HG 16
#define TLEN 1024
#define NCLS 192
#define EMAX 4194304

typedef unsigned long long ull;

// ------------------------- scratch (no cudaMalloc allowed) -------------------
__device__ __align__(16) int   g_degi[NN];
__device__ __align__(16) float g_dinv[NN];
__device__ __align__(16) int   g_eoff[NN];
__device__ __align__(16) int   g_ecur[NN];
__device__ __align__(16) int   g_part[512];
__device__ __align__(16) int   g_psum[512];
__device__ __align__(16) int2  g_epk[EMAX];                         // {src, dinv[src]}
__device__ __align__(16) float g_xw[NN * HG];
__device__ __align__(16) float g_agg[NN * HG];
__device__ __align__(16) int   g_starts[NG];
__device__ __align__(16) float g_seq0[(size_t)NG * TLEN * HG];      // 33.5 MB
__device__ __align__(16) float g_h0[(size_t)NG * TLEN * 64];        // 134 MB
__device__ __align__(16) float g_pre[(size_t)2 * NG * TLEN * 128];  // 537 MB
__device__ __align__(16) float g_pooled[NG * 64];

// ------------------------- helpers ------------------------------------------
__device__ __forceinline__ ull pk2(float lo, float hi) {
    ull v; asm("mov.b64 %0, {%1, %2};" : "=l"(v) : "f"(lo), "f"(hi)); return v;
}
__device__ __forceinline__ void upk2(ull v, float& lo, float& hi) {
    asm("mov.b64 {%0, %1}, %2;" : "=f"(lo), "=f"(hi) : "l"(v));
}
#define FMA2(d, a, b) asm("fma.rn.f32x2 %0, %1, %2, %0;" : "+l"(d) : "l"(a), "l"(b))

__device__ __forceinline__ float tanh_fast(float x) {
    float y; asm("tanh.approx.f32 %0, %1;" : "=f"(y) : "f"(x)); return y;
}
__device__ __forceinline__ float sig_fast(float x) {
    return fmaf(0.5f, tanh_fast(0.5f * x), 0.5f);
}

// ------------------------- init + degree + scan + fill -----------------------
__global__ void init_kernel() {
    int idx = blockIdx.x * 256 + threadIdx.x;
    if (idx < (int)(NG * TLEN * HG / 4))
        ((float4*)g_seq0)[idx] = make_float4(0.f, 0.f, 0.f, 0.f);
    if (idx < NN) g_degi[idx] = 0;
}

__global__ void deg_kernel(const int* __restrict__ dst, int E) {
    int e = blockIdx.x * 256 + threadIdx.x;
    if (e < E) atomicAdd(&g_degi[dst[e]], 1);
}

// block sums of g_degi (256 per block, 512 blocks)
__global__ void scan1_kernel() {
    __shared__ int sh[256];
    int tid = threadIdx.x;
    sh[tid] = g_degi[blockIdx.x * 256 + tid];
    __syncthreads();
    for (int o = 128; o > 0; o >>= 1) {
        if (tid < o) sh[tid] += sh[tid + o];
        __syncthreads();
    }
    if (tid == 0) g_part[blockIdx.x] = sh[0];
}

// exclusive scan of 512 partials (single block)
__global__ void scan2_kernel() {
    __shared__ int sh[512];
    int tid = threadIdx.x;
    sh[tid] = g_part[tid];
    __syncthreads();
    int v;
    for (int o = 1; o < 512; o <<= 1) {
        v = (tid >= o) ? sh[tid - o] : 0;
        __syncthreads();
        sh[tid] += v;
        __syncthreads();
    }
    g_psum[tid] = (tid == 0) ? 0 : sh[tid - 1];
}

// per-node exclusive offsets + dinv
__global__ void scan3_kernel() {
    __shared__ int sh[256];
    int tid = threadIdx.x;
    int n = blockIdx.x * 256 + tid;
    int d = g_degi[n];
    sh[tid] = d;
    __syncthreads();
    int v;
    for (int o = 1; o < 256; o <<= 1) {
        v = (tid >= o) ? sh[tid - o] : 0;
        __syncthreads();
        sh[tid] += v;
        __syncthreads();
    }
    int off = g_psum[blockIdx.x] + sh[tid] - d;   // exclusive
    g_eoff[n] = off;
    g_ecur[n] = off;
    g_dinv[n] = rsqrtf((float)(d + 1));           // +1 self-loop
}

__global__ void fill_kernel(const int* __restrict__ src, const int* __restrict__ dst, int E) {
    int e = blockIdx.x * 256 + threadIdx.x;
    if (e >= E) return;
    int s = src[e], d = dst[e];
    int pos = atomicAdd(&g_ecur[d], 1);
    g_epk[pos] = make_int2(s, __float_as_int(g_dinv[s]));
}

// ------------------------- GCN feature transform -----------------------------
__global__ __launch_bounds__(256) void xw1_kernel(const float* __restrict__ x,
                                                  const float* __restrict__ W) {
    __shared__ float Ws[FIN * HG];
    __shared__ float Xs[16 * FIN];
    int tid = threadIdx.x;
    for (int i = tid; i < FIN * HG; i += 256) Ws[i] = W[i];
    size_t base = (size_t)blockIdx.x * 16 * FIN;
    for (int i = tid; i < 16 * FIN; i += 256) Xs[i] = x[base + i];
    __syncthreads();
    int nl = tid >> 4, j = tid & 15;
    const float* xr = Xs + nl * FIN;
    float acc = 0.f;
#pragma unroll
    for (int d = 0; d < FIN; d++) acc = fmaf(xr[d], Ws[d * HG + j], acc);
    g_xw[(size_t)blockIdx.x * 256 + tid] = acc;
}

__global__ __launch_bounds__(256) void xw2_kernel(const float* __restrict__ W) {
    __shared__ float Ws[HG * HG];
    __shared__ float Xs[16 * HG];
    int tid = threadIdx.x;
    if (tid < HG * HG) Ws[tid] = W[tid];
    size_t base = (size_t)blockIdx.x * 16 * HG;
    if (tid < 64) ((float4*)Xs)[tid] = ((const float4*)(g_agg + base))[tid];
    __syncthreads();
    int nl = tid >> 4, j = tid & 15;
    const float* xr = Xs + nl * HG;
    float acc = 0.f;
#pragma unroll
    for (int d = 0; d < HG; d++) acc = fmaf(fmaxf(xr[d], 0.f), Ws[d * HG + j], acc);
    g_xw[(size_t)blockIdx.x * 256 + tid] = acc;
}

// ------------------------- gather-based conv ---------------------------------
__global__ __launch_bounds__(256) void conv_kernel(const float* __restrict__ bias) {
    int n = blockIdx.x * 256 + threadIdx.x;
    if (n >= NN) return;
    int e0 = g_eoff[n];
    int e1 = e0 + g_degi[n];
    float4 a0 = make_float4(0.f, 0.f, 0.f, 0.f), a1 = a0, a2 = a0, a3 = a0;
#pragma unroll 4
    for (int e = e0; e < e1; e++) {
        int2 pk = g_epk[e];
        int s = pk.x;
        float nr = __int_as_float(pk.y);
        const float4* xs = (const float4*)(g_xw + (size_t)s * HG);
        float4 v0 = xs[0], v1 = xs[1], v2 = xs[2], v3 = xs[3];
        a0.x = fmaf(nr, v0.x, a0.x); a0.y = fmaf(nr, v0.y, a0.y);
        a0.z = fmaf(nr, v0.z, a0.z); a0.w = fmaf(nr, v0.w, a0.w);
        a1.x = fmaf(nr, v1.x, a1.x); a1.y = fmaf(nr, v1.y, a1.y);
        a1.z = fmaf(nr, v1.z, a1.z); a1.w = fmaf(nr, v1.w, a1.w);
        a2.x = fmaf(nr, v2.x, a2.x); a2.y = fmaf(nr, v2.y, a2.y);
        a2.z = fmaf(nr, v2.z, a2.z); a2.w = fmaf(nr, v2.w, a2.w);
        a3.x = fmaf(nr, v3.x, a3.x); a3.y = fmaf(nr, v3.y, a3.y);
        a3.z = fmaf(nr, v3.z, a3.z); a3.w = fmaf(nr, v3.w, a3.w);
    }
    float di = g_dinv[n];
    float d2 = di * di;
    const float4* xn = (const float4*)(g_xw + (size_t)n * HG);
    const float4* bb = (const float4*)bias;
    float4* out = (float4*)(g_agg + (size_t)n * HG);
    float4 q, b, w;
#define EMIT(acc, k) \
    w = xn[k]; b = bb[k]; \
    q.x = b.x + di * acc.x + d2 * w.x; q.y = b.y + di * acc.y + d2 * w.y; \
    q.z = b.z + di * acc.z + d2 * w.z; q.w = b.w + di * acc.w + d2 * w.w; \
    out[k] = q;
    EMIT(a0, 0) EMIT(a1, 1) EMIT(a2, 2) EMIT(a3, 3)
#undef EMIT
}

// ------------------------- ragged -> padded ---------------------------------
__global__ void starts_kernel(const int* __restrict__ batch) {
    int i = blockIdx.x * 256 + threadIdx.x;
    if (i >= NN) return;
    int b = batch[i];
    int bp = (i == 0) ? -1 : batch[i - 1];
    for (int g = bp + 1; g <= b; ++g) g_starts[g] = i;   // batch is sorted
}

__global__ void pack_kernel(const int* __restrict__ batch) {
    int idx = blockIdx.x * 256 + threadIdx.x;
    if (idx >= NN * 4) return;
    int n = idx >> 2, q = idx & 3;
    int g = batch[n];
    int pos = n - g_starts[g];
    if (pos >= TLEN) return;  // mode="drop"
    float4 v = ((const float4*)(g_agg + (size_t)n * HG))[q];
    v.x = fmaxf(v.x, 0.f); v.y = fmaxf(v.y, 0.f);
    v.z = fmaxf(v.z, 0.f); v.w = fmaxf(v.w, 0.f);
    ((float4*)(g_seq0 + ((size_t)g * TLEN + pos) * HG))[q] = v;
}

// ------------------------- LSTM input projection (batch GEMM) ----------------
template<int DIN>
__global__ __launch_bounds__(256) void gemm_pre_kernel(
    const float* __restrict__ X,      // [NG][TLEN][DIN]
    const float* __restrict__ wih,    // [2][128][DIN]
    const float* __restrict__ bih, const float* __restrict__ bhh) // [2][128]
{
    constexpr int WPAD = DIN + 4;
    constexpr int TT = 64;
    constexpr int TPG = 8;
    __shared__ float Ws[128 * WPAD];
    __shared__ float Bs[128];
    __shared__ float Xs[TT * DIN];

    int dir = blockIdx.z, row = blockIdx.y;
    int tb = blockIdx.x * TT;
    int tid = threadIdx.x;

    const float* Wg = wih + (size_t)dir * 128 * DIN;
    for (int i = tid; i < 128 * DIN; i += 256) {
        int r = i / DIN, k = i - r * DIN;
        Ws[r * WPAD + k] = Wg[i];
    }
    if (tid < 128) Bs[tid] = bih[dir * 128 + tid] + bhh[dir * 128 + tid];
    const float4* Xg = (const float4*)(X + ((size_t)row * TLEN + tb) * DIN);
    for (int i = tid; i < TT * DIN / 4; i += 256) ((float4*)Xs)[i] = Xg[i];
    __syncthreads();

    int j = tid & 31, grp = tid >> 5;
    const float* xb = Xs + grp * TPG * DIN;
    const float* w0 = Ws + (0 * 32 + j) * WPAD;
    const float* w1 = Ws + (1 * 32 + j) * WPAD;
    const float* w2 = Ws + (2 * 32 + j) * WPAD;
    const float* w3 = Ws + (3 * 32 + j) * WPAD;

    ull acc[TPG][4];
#pragma unroll
    for (int tt = 0; tt < TPG; tt++)
#pragma unroll
        for (int g = 0; g < 4; g++) acc[tt][g] = 0ull;

#pragma unroll
    for (int k = 0; k < DIN; k += 4) {
        ulonglong2 wv0 = *(const ulonglong2*)(w0 + k);
        ulonglong2 wv1 = *(const ulonglong2*)(w1 + k);
        ulonglong2 wv2 = *(const ulonglong2*)(w2 + k);
        ulonglong2 wv3 = *(const ulonglong2*)(w3 + k);
#pragma unroll
        for (int tt = 0; tt < TPG; tt++) {
            ulonglong2 xv = *(const ulonglong2*)(xb + tt * DIN + k);
            FMA2(acc[tt][0], xv.x, wv0.x); FMA2(acc[tt][0], xv.y, wv0.y);
            FMA2(acc[tt][1], xv.x, wv1.x); FMA2(acc[tt][1], xv.y, wv1.y);
            FMA2(acc[tt][2], xv.x, wv2.x); FMA2(acc[tt][2], xv.y, wv2.y);
            FMA2(acc[tt][3], xv.x, wv3.x); FMA2(acc[tt][3], xv.y, wv3.y);
        }
    }

    float b0 = Bs[j], b1 = Bs[32 + j], b2 = Bs[64 + j], b3 = Bs[96 + j];
    float4* Og = (float4*)(g_pre + (((size_t)dir * NG + row) * TLEN + tb + grp * TPG) * 128) + j;
#pragma unroll
    for (int tt = 0; tt < TPG; tt++) {
        float lo, hi; float4 o;
        upk2(acc[tt][0], lo, hi); o.x = lo + hi + b0;
        upk2(acc[tt][1], lo, hi); o.y = lo + hi + b1;
        upk2(acc[tt][2], lo, hi); o.z = lo + hi + b2;
        upk2(acc[tt][3], lo, hi); o.w = lo + hi + b3;
        Og[(size_t)tt * 32] = o;
    }
}

// ------------------------- LSTM recurrence -----------------------------------
// One warp per (row, dir); thread j owns hidden unit j. 4-deep register
// prefetch ring on the pre-activation stream (g_pre is DRAM-resident,
// lat ~577 cyc; 3 outstanding loads x ~220 cyc/step covers it).
template<bool IS_L0>
__global__ __launch_bounds__(32) void lstm_rec_kernel(const float* __restrict__ whh)
{
    int row = blockIdx.x, dir = blockIdx.y;
    int j = threadIdx.x;
    const float4* P = (const float4*)(g_pre + ((size_t)dir * NG + row) * TLEN * 128) + j;
    float* O = g_h0 + (size_t)row * TLEN * 64 + dir * 32 + j;

    ulonglong2 w[4][8];
#pragma unroll
    for (int g = 0; g < 4; g++) {
        const ulonglong2* wp = (const ulonglong2*)(whh + ((size_t)dir * 128 + g * 32 + j) * 32);
#pragma unroll
        for (int q = 0; q < 8; q++) w[g][q] = wp[q];
    }

    __shared__ __align__(16) float h_s[2][32];
    h_s[0][j] = 0.f;
    __syncwarp();

    int t0 = dir ? (TLEN - 1) : 0;
    int dt = dir ? -1 : 1;
    float c = 0.f, pool = 0.f;
    int buf = 0;

#define LOADP(s_) P[(size_t)(t0 + (s_) * dt) * 32]

#define STEP(pp, s_) { \
    ull a0 = pk2(pp.x, 0.f), a1 = pk2(pp.y, 0.f); \
    ull a2 = pk2(pp.z, 0.f), a3 = pk2(pp.w, 0.f); \
    const ulonglong2* hv = (const ulonglong2*)h_s[buf]; \
    _Pragma("unroll") \
    for (int q = 0; q < 8; q++) { \
        ulonglong2 hh = hv[q]; \
        FMA2(a0, hh.x, w[0][q].x); FMA2(a0, hh.y, w[0][q].y); \
        FMA2(a1, hh.x, w[1][q].x); FMA2(a1, hh.y, w[1][q].y); \
        FMA2(a2, hh.x, w[2][q].x); FMA2(a2, hh.y, w[2][q].y); \
        FMA2(a3, hh.x, w[3][q].x); FMA2(a3, hh.y, w[3][q].y); \
    } \
    float lo, hi; \
    upk2(a0, lo, hi); float gi = sig_fast(lo + hi); \
    upk2(a1, lo, hi); float gf = sig_fast(lo + hi); \
    upk2(a2, lo, hi); float gg = tanh_fast(lo + hi); \
    upk2(a3, lo, hi); float go = sig_fast(lo + hi); \
    c = gf * c + gi * gg; \
    float h = go * tanh_fast(c); \
    if (IS_L0) O[(size_t)(t0 + (s_) * dt) * 64] = h; \
    else       pool += h; \
    h_s[buf ^ 1][j] = h; \
    __syncwarp(); \
    buf ^= 1; }

    float4 p0 = LOADP(0);
    float4 p1 = LOADP(1);
    float4 p2 = LOADP(2);
    for (int s = 0; s < TLEN; s += 4) {
        float4 p3 = (s + 3 < TLEN) ? LOADP(s + 3) : p0;
        STEP(p0, s)
        float4 q0 = (s + 4 < TLEN) ? LOADP(s + 4) : p0;
        STEP(p1, s + 1)
        float4 q1 = (s + 5 < TLEN) ? LOADP(s + 5) : p0;
        STEP(p2, s + 2)
        float4 q2 = (s + 6 < TLEN) ? LOADP(s + 6) : p0;
        STEP(p3, s + 3)
        p0 = q0; p1 = q1; p2 = q2;
    }
#undef STEP
#undef LOADP
    if (!IS_L0) g_pooled[row * 64 + dir * 32 + j] = pool;
}

// ------------------------- FC + mean ----------------------------------------
__global__ void fc_kernel(const float* __restrict__ w, const float* __restrict__ b,
                          float* __restrict__ out) {
    int idx = blockIdx.x * 256 + threadIdx.x;
    if (idx >= NG * NCLS) return;
    int r = idx / NCLS, cc = idx - r * NCLS;
    const float* p = g_pooled + r * 64;
    float acc = 0.f;
#pragma unroll
    for (int k = 0; k < 64; k++) acc += p[k] * w[k * NCLS + cc];
    out[idx] = b[cc] + acc * (1.f / (float)TLEN);
}

// ------------------------- launch -------------------------------------------
extern "C" void kernel_launch(void* const* d_in, const int* in_sizes, int n_in,
                              void* d_out, int out_size) {
    const float* x     = (const float*)d_in[0];
    const int*   ei    = (const int*)d_in[1];
    const int*   batch = (const int*)d_in[2];
    const float* w1    = (const float*)d_in[3];
    const float* b1    = (const float*)d_in[4];
    const float* w2    = (const float*)d_in[5];
    const float* b2    = (const float*)d_in[6];
    const float* l0wih = (const float*)d_in[7];
    const float* l0whh = (const float*)d_in[8];
    const float* l0bih = (const float*)d_in[9];
    const float* l0bhh = (const float*)d_in[10];
    const float* l1wih = (const float*)d_in[11];
    const float* l1whh = (const float*)d_in[12];
    const float* l1bih = (const float*)d_in[13];
    const float* l1bhh = (const float*)d_in[14];
    const float* fcw   = (const float*)d_in[15];
    const float* fcb   = (const float*)d_in[16];
    float* out = (float*)d_out;

    int E = in_sizes[1] / 2;
    const int* src = ei;
    const int* dst = ei + E;

    float* seq0_p; cudaGetSymbolAddress((void**)&seq0_p, g_seq0);
    float* h0_p;   cudaGetSymbolAddress((void**)&h0_p, g_h0);

    // CSR build
    init_kernel<<<8192, 256>>>();                          // launch 0
    deg_kernel<<<(E + 255) / 256, 256>>>(dst, E);          // launch 1
    scan1_kernel<<<512, 256>>>();                          // launch 2

    // PROBE (launch 3 = the one ncu profiles): 1/16-scale gemm_pre<64> on
    // whatever is in g_h0 (zeros on first run). Its g_pre output region is
    // fully overwritten by the real gemm_pre<16> below, so the final output
    // is unaffected. Purpose: direct roofline/duration measurement of the
    // suspected dominant kernel.
    gemm_pre_kernel<64><<<dim3(TLEN / 64, 64, 1), 256>>>(h0_p, l1wih, l1bih, l1bhh);

    scan2_kernel<<<1, 512>>>();                            // launch 4
    scan3_kernel<<<512, 256>>>();                          // launch 5
    fill_kernel<<<(E + 255) / 256, 256>>>(src, dst, E);

    // conv1 + conv2 (gather-based)
    xw1_kernel<<<NN / 16, 256>>>(x, w1);
    conv_kernel<<<NN / 256, 256>>>(b1);
    xw2_kernel<<<NN / 16, 256>>>(w2);
    conv_kernel<<<NN / 256, 256>>>(b2);

    // pack
    starts_kernel<<<(NN + 255) / 256, 256>>>(batch);
    pack_kernel<<<(NN * 4 + 255) / 256, 256>>>(batch);

    // BiLSTM layer 0
    gemm_pre_kernel<HG><<<dim3(TLEN / 64, NG, 2), 256>>>(seq0_p, l0wih, l0bih, l0bhh);
    lstm_rec_kernel<true><<<dim3(NG, 2), 32>>>(l0whh);

    // BiLSTM layer 1 (fuses mean pooling)
    gemm_pre_kernel<64><<<dim3(TLEN / 64, NG, 2), 256>>>(h0_p, l1wih, l1bih, l1bhh);
    lstm_rec_kernel<false><<<dim3(NG, 2), 32>>>(l1whh);

    fc_kernel<<<(NG * NCLS + 255) / 256, 256>>>(fcw, fcb, out);
}